// round 2
// baseline (speedup 1.0000x reference)
#include <cuda_runtime.h>

#define NPTS 16384
#define KNN  16

__device__ int g_nbr[NPTS * KNN];

typedef unsigned long long ull;

__device__ __forceinline__ ull pk2(float lo, float hi) {
    ull r; asm("mov.b64 %0, {%1,%2};" : "=l"(r) : "f"(lo), "f"(hi)); return r;
}
__device__ __forceinline__ void upk2(ull v, float& lo, float& hi) {
    asm("mov.b64 {%0,%1}, %2;" : "=f"(lo), "=f"(hi) : "l"(v));
}
__device__ __forceinline__ ull ffma2(ull a, ull b, ull c) {
    ull d; asm("fma.rn.f32x2 %0, %1, %2, %3;" : "=l"(d) : "l"(a), "l"(b), "l"(c)); return d;
}

// ---------------------------------------------------------------------------
// KNN: exact top-16 by squared distance, lexicographic (d2, idx) tie-break
// (matches jax top_k stability; includes self like loop=True).
// 4 threads per target, each scans a strided quarter, merge via smem.
// ---------------------------------------------------------------------------
__device__ __forceinline__ void topk_insert(float (&bd)[16], int (&bi)[16], float d, int j) {
    if (d < bd[15] || (d == bd[15] && j < bi[15])) {
        bd[15] = d; bi[15] = j;
#pragma unroll
        for (int q = 15; q > 0; --q) {
            bool sw = (bd[q] < bd[q-1]) || (bd[q] == bd[q-1] && bi[q] < bi[q-1]);
            if (sw) {
                float td = bd[q-1]; bd[q-1] = bd[q]; bd[q] = td;
                int   ti = bi[q-1]; bi[q-1] = bi[q]; bi[q] = ti;
            }
        }
    }
}

__global__ __launch_bounds__(128)
void knn_kernel(const float* __restrict__ pos) {
    __shared__ float4 tile[1024];
    __shared__ float  md[32 * 64];
    __shared__ int    mi[32 * 64];

    int t  = threadIdx.x;
    int tl = t >> 2;        // local target 0..31
    int sp = t & 3;         // split 0..3
    int target = blockIdx.x * 32 + tl;

    float px = pos[3*target], py = pos[3*target+1], pz = pos[3*target+2];
    float sqt = px*px + py*py + pz*pz;

    float bd[16]; int bi[16];
#pragma unroll
    for (int r = 0; r < 16; r++) { bd[r] = 3.0e38f; bi[r] = 0x7fffffff; }

    for (int base = 0; base < NPTS; base += 1024) {
        __syncthreads();
        for (int i = t; i < 1024; i += 128) {
            int g = base + i;
            float x = pos[3*g], y = pos[3*g+1], z = pos[3*g+2];
            tile[i] = make_float4(x, y, z, x*x + y*y + z*z);
        }
        __syncthreads();
        for (int i = sp; i < 1024; i += 4) {
            float4 q = tile[i];
            float dot = px*q.x + py*q.y + pz*q.z;
            float d2  = sqt + q.w - 2.0f * dot;   // same expansion as reference
            topk_insert(bd, bi, d2, base + i);
        }
    }

    int mb = tl * 64 + sp * 16;
#pragma unroll
    for (int r = 0; r < 16; r++) { md[mb + r] = bd[r]; mi[mb + r] = bi[r]; }
    __syncthreads();

    if (sp == 0) {
        for (int c = 16; c < 64; c++)
            topk_insert(bd, bi, md[tl*64 + c], mi[tl*64 + c]);
#pragma unroll
        for (int r = 0; r < 16; r++)
            g_nbr[target * KNN + r] = bi[r];
    }
}

// ---------------------------------------------------------------------------
// Fused PointNet conv layer:
//   m = [x_j, pos_j - pos_i]  -> m @ Wa + ba -> GroupNorm(8-ch groups) -> ReLU
//   -> h @ Wb + bb -> max over 16 neighbors -> ReLU
// One thread per edge (TPE=1) or per edge-half (TPE=2, 64 channels each).
// All GEMMs use packed fma.rn.f32x2; weights/messages/h live in smem.
// ---------------------------------------------------------------------------
template<bool FIRST, int IN_DIM, int C_IN, int C_OUT, int NPB, int TPE>
__global__ __launch_bounds__(NPB * 16 * TPE, 1)
void conv_kernel(const float* __restrict__ x, const float* __restrict__ pos,
                 const float* __restrict__ normal,
                 const float* __restrict__ Wa, const float* __restrict__ ba,
                 const float* __restrict__ gam, const float* __restrict__ bet,
                 const float* __restrict__ Wb, const float* __restrict__ bb,
                 float* __restrict__ out)
{
    constexpr int T  = NPB * 16 * TPE;
    constexpr int NE = NPB * 16;
    constexpr int CH = C_OUT / TPE;   // output channels owned by this thread
    constexpr int HS = C_OUT + 1;     // padded h row stride (conflict-free)

    extern __shared__ float sm[];
    float* Wa_s = sm;
    float* Wb_s = Wa_s + IN_DIM * C_OUT;
    float* ba_s = Wb_s + C_OUT * C_OUT;
    float* g_s  = ba_s + C_OUT;
    float* be_s = g_s  + C_OUT;
    float* bb_s = be_s + C_OUT;
    float* h_s  = bb_s + C_OUT;
    float* m_s  = h_s  + NE * HS;     // stride IN_DIM (odd -> conflict-free)

    int t = threadIdx.x;

    {   // cooperative weight load
        const float4* s1 = (const float4*)Wa; float4* d1 = (float4*)Wa_s;
        for (int i = t; i < IN_DIM * C_OUT / 4; i += T) d1[i] = s1[i];
        const float4* s2 = (const float4*)Wb; float4* d2 = (float4*)Wb_s;
        for (int i = t; i < C_OUT * C_OUT / 4; i += T) d2[i] = s2[i];
        for (int i = t; i < C_OUT; i += T) {
            ba_s[i] = ba[i]; g_s[i] = gam[i]; be_s[i] = bet[i]; bb_s[i] = bb[i];
        }
    }

    int edge = (TPE == 2) ? (t >> 1) : t;
    int half = (TPE == 2) ? (t & 1)  : 0;
    int e    = edge & 15;
    int node = blockIdx.x * NPB + (edge >> 4);
    int j    = g_nbr[node * KNN + e];

    float* m_row = m_s + edge * IN_DIM;
    float pix = pos[3*node], piy = pos[3*node+1], piz = pos[3*node+2];
    float pjx = pos[3*j],    pjy = pos[3*j+1],    pjz = pos[3*j+2];

    if (FIRST) {
        if (half == 0) {
            m_row[0] = pjx; m_row[1] = pjy; m_row[2] = pjz;
            m_row[3] = normal[3*j]; m_row[4] = normal[3*j+1]; m_row[5] = normal[3*j+2];
            m_row[6] = pjx - pix; m_row[7] = pjy - piy; m_row[8] = pjz - piz;
        }
    } else {
        const float4* xr = (const float4*)(x + (size_t)j * C_IN);
#pragma unroll
        for (int q = half; q < C_IN / 4; q += TPE) {
            float4 v = xr[q];
            m_row[4*q]   = v.x; m_row[4*q+1] = v.y;
            m_row[4*q+2] = v.z; m_row[4*q+3] = v.w;
        }
        if (half == TPE - 1) {
            m_row[C_IN]   = pjx - pix;
            m_row[C_IN+1] = pjy - piy;
            m_row[C_IN+2] = pjz - piz;
        }
    }
    __syncthreads();

    float* h_row = h_s + edge * HS;

    // --- GEMM1 + GroupNorm + ReLU ---
    for (int c0 = half * CH; c0 < half * CH + CH; c0 += 32) {
        ull acc[16];
#pragma unroll
        for (int q = 0; q < 16; q++) acc[q] = pk2(ba_s[c0 + 2*q], ba_s[c0 + 2*q + 1]);
#pragma unroll 4
        for (int k = 0; k < IN_DIM; k++) {
            float mk = m_row[k];
            ull mk2 = pk2(mk, mk);
            const ulonglong2* w = (const ulonglong2*)(Wa_s + k * C_OUT + c0);
#pragma unroll
            for (int q = 0; q < 8; q++) {
                ulonglong2 ww = w[q];
                acc[2*q]   = ffma2(mk2, ww.x, acc[2*q]);
                acc[2*q+1] = ffma2(mk2, ww.y, acc[2*q+1]);
            }
        }
        float f[32];
#pragma unroll
        for (int q = 0; q < 16; q++) upk2(acc[q], f[2*q], f[2*q+1]);
#pragma unroll
        for (int g = 0; g < 4; g++) {        // 8-channel GN groups (all layers)
            float s = 0.0f;
#pragma unroll
            for (int i = 0; i < 8; i++) s += f[g*8 + i];
            float mu = s * 0.125f;
            float vs = 0.0f;
#pragma unroll
            for (int i = 0; i < 8; i++) { float d = f[g*8 + i] - mu; vs += d * d; }
            float inv = rsqrtf(vs * 0.125f + 1e-5f);
#pragma unroll
            for (int i = 0; i < 8; i++) {
                int c = c0 + g*8 + i;
                float yv = (f[g*8 + i] - mu) * inv * g_s[c] + be_s[c];
                h_row[c] = fmaxf(yv, 0.0f);
            }
        }
    }
    __syncwarp();   // TPE=2: partner half's h channels must be visible

    // --- GEMM2 + neighbor-max + ReLU ---
    for (int c0 = half * CH; c0 < half * CH + CH; c0 += 32) {
        ull acc[16];
#pragma unroll
        for (int q = 0; q < 16; q++) acc[q] = pk2(bb_s[c0 + 2*q], bb_s[c0 + 2*q + 1]);
#pragma unroll 4
        for (int k = 0; k < C_OUT; k++) {
            float hk = h_row[k];
            ull hk2 = pk2(hk, hk);
            const ulonglong2* w = (const ulonglong2*)(Wb_s + k * C_OUT + c0);
#pragma unroll
            for (int q = 0; q < 8; q++) {
                ulonglong2 ww = w[q];
                acc[2*q]   = ffma2(hk2, ww.x, acc[2*q]);
                acc[2*q+1] = ffma2(hk2, ww.y, acc[2*q+1]);
            }
        }
        float f[32];
#pragma unroll
        for (int q = 0; q < 16; q++) upk2(acc[q], f[2*q], f[2*q+1]);
#pragma unroll
        for (int i = 0; i < 32; i++) {
            float v = f[i];
            if (TPE == 2) {   // lane = e*2 + half; reduce over e bits 1..4
                v = fmaxf(v, __shfl_xor_sync(0xffffffffu, v, 2));
                v = fmaxf(v, __shfl_xor_sync(0xffffffffu, v, 4));
                v = fmaxf(v, __shfl_xor_sync(0xffffffffu, v, 8));
                v = fmaxf(v, __shfl_xor_sync(0xffffffffu, v, 16));
            } else {          // lane = ... e in bits 0..3 within 16-lane group
                v = fmaxf(v, __shfl_xor_sync(0xffffffffu, v, 1));
                v = fmaxf(v, __shfl_xor_sync(0xffffffffu, v, 2));
                v = fmaxf(v, __shfl_xor_sync(0xffffffffu, v, 4));
                v = fmaxf(v, __shfl_xor_sync(0xffffffffu, v, 8));
            }
            f[i] = v;
        }
        if (e == 0) {
#pragma unroll
            for (int i = 0; i < 32; i++)
                out[(size_t)node * C_OUT + c0 + i] = fmaxf(f[i], 0.0f);  // outer ReLU
        }
    }
}

// ---------------------------------------------------------------------------

static constexpr int SM1 = (9*64   + 64*64   + 4*64  + 256*65  + 256*9 ) * 4; //  95,488 B
static constexpr int SM2 = (67*64  + 64*64   + 4*64  + 256*65  + 256*67) * 4; // 169,728 B
static constexpr int SM3 = (67*128 + 128*128 + 4*128 + 128*129 + 128*67) * 4; // 202,240 B

extern "C" void kernel_launch(void* const* d_in, const int* in_sizes, int n_in,
                              void* d_out, int out_size)
{
    const float* pos    = (const float*)d_in[0];
    const float* normal = (const float*)d_in[1];
    const float* W1a = (const float*)d_in[2];
    const float* b1a = (const float*)d_in[3];
    const float* g1  = (const float*)d_in[4];
    const float* be1 = (const float*)d_in[5];
    const float* W1b = (const float*)d_in[6];
    const float* b1b = (const float*)d_in[7];
    const float* W2a = (const float*)d_in[8];
    const float* b2a = (const float*)d_in[9];
    const float* g2  = (const float*)d_in[10];
    const float* be2 = (const float*)d_in[11];
    const float* W2b = (const float*)d_in[12];
    const float* b2b = (const float*)d_in[13];
    const float* W3a = (const float*)d_in[14];
    const float* b3a = (const float*)d_in[15];
    const float* g3  = (const float*)d_in[16];
    const float* be3 = (const float*)d_in[17];
    const float* W3b = (const float*)d_in[18];
    const float* b3b = (const float*)d_in[19];

    float* out = (float*)d_out;
    float* h1 = out;                            // [N,64]
    float* h2 = out + (size_t)NPTS * 64;        // [N,64]
    float* h3 = out + (size_t)NPTS * 128;       // [N,128]

    cudaFuncSetAttribute(conv_kernel<true,  9, 6,  64, 16, 1>,
                         cudaFuncAttributeMaxDynamicSharedMemorySize, SM1);
    cudaFuncSetAttribute(conv_kernel<false, 67, 64, 64, 16, 1>,
                         cudaFuncAttributeMaxDynamicSharedMemorySize, SM2);
    cudaFuncSetAttribute(conv_kernel<false, 67, 64, 128, 8, 2>,
                         cudaFuncAttributeMaxDynamicSharedMemorySize, SM3);

    knn_kernel<<<NPTS / 32, 128>>>(pos);

    conv_kernel<true, 9, 6, 64, 16, 1><<<NPTS / 16, 256, SM1>>>(
        nullptr, pos, normal, W1a, b1a, g1, be1, W1b, b1b, h1);

    conv_kernel<false, 67, 64, 64, 16, 1><<<NPTS / 16, 256, SM2>>>(
        h1, pos, nullptr, W2a, b2a, g2, be2, W2b, b2b, h2);

    conv_kernel<false, 67, 64, 128, 8, 2><<<NPTS / 8, 256, SM3>>>(
        h2, pos, nullptr, W3a, b3a, g3, be3, W3b, b3b, h3);
}

// round 3
// speedup vs baseline: 2.5706x; 2.5706x over previous
#include <cuda_runtime.h>

#define NPTS 16384

__device__ int g_nbr[NPTS * 16];

typedef unsigned long long ull;

__device__ __forceinline__ ull pk2(float lo, float hi) {
    ull r; asm("mov.b64 %0, {%1,%2};" : "=l"(r) : "f"(lo), "f"(hi)); return r;
}
__device__ __forceinline__ void upk2(ull v, float& lo, float& hi) {
    asm("mov.b64 {%0,%1}, %2;" : "=f"(lo), "=f"(hi) : "l"(v));
}
__device__ __forceinline__ ull ffma2(ull a, ull b, ull c) {
    ull d; asm("fma.rn.f32x2 %0, %1, %2, %3;" : "=l"(d) : "l"(a), "l"(b), "l"(c)); return d;
}

// ---------------------------------------------------------------------------
// KNN: one warp per target. Distributed sorted top-16 list (one entry per
// lane, ascending by (d2, idx) lex). Inserts are warp-uniform ballot ops —
// no divergent serial insertion.
// ---------------------------------------------------------------------------
__global__ __launch_bounds__(256)
void knn_kernel(const float* __restrict__ pos) {
    __shared__ float4 tile[2048];
    int tid  = threadIdx.x;
    int lane = tid & 31;
    int t    = blockIdx.x * 8 + (tid >> 5);

    float px = pos[3*t], py = pos[3*t+1], pz = pos[3*t+2];
    float sqt = px*px + py*py + pz*pz;

    float kd = 3.0e38f; int ki = 0x7fffffff;   // this lane's list entry
    float wd = 3.0e38f; int wi = 0x7fffffff;   // 16th-best (lane 15) shadow

    for (int base = 0; base < NPTS; base += 2048) {
        __syncthreads();
        for (int i = tid; i < 2048; i += 256) {
            int g = base + i;
            float x = pos[3*g], y = pos[3*g+1], z = pos[3*g+2];
            tile[i] = make_float4(x, y, z, x*x + y*y + z*z);
        }
        __syncthreads();
        for (int it = 0; it < 2048; it += 32) {
            float4 q = tile[it + lane];
            float dot = px*q.x + py*q.y + pz*q.z;
            float d2  = sqt + q.w - 2.0f*dot;   // same expansion as reference
            int   c   = base + it + lane;
            while (true) {
                bool p = (d2 < wd) || (d2 == wd && c < wi);
                unsigned bal = __ballot_sync(0xffffffffu, p);
                if (!bal) break;
                int   src = __ffs(bal) - 1;
                float ds  = __shfl_sync(0xffffffffu, d2, src);
                int   is  = __shfl_sync(0xffffffffu, c,  src);
                // distributed sorted insert
                bool gt = (kd > ds) || (kd == ds && ki > is);
                unsigned mv = __ballot_sync(0xffffffffu, gt);
                float pd = __shfl_up_sync(0xffffffffu, kd, 1);
                int   pi = __shfl_up_sync(0xffffffffu, ki, 1);
                int   ip = __ffs(mv) - 1;
                if (gt) {
                    if (lane == ip) { kd = ds; ki = is; }
                    else            { kd = pd; ki = pi; }
                }
                wd = __shfl_sync(0xffffffffu, kd, 15);
                wi = __shfl_sync(0xffffffffu, ki, 15);
                if (lane == src) d2 = 3.0e38f;   // consumed
            }
        }
    }
    if (lane < 16) g_nbr[t*16 + lane] = ki;
}

// ---------------------------------------------------------------------------
// Conv layer: register-blocked GEMM, 4 edges x 16 channels per thread.
// ---------------------------------------------------------------------------
#define GETK(v,kk) ((kk)==0?(v).x:(kk)==1?(v).y:(kk)==2?(v).z:(v).w)

#define FMA_ROW(q, u) \
    acc[q][0]=ffma2(u,wA.x,acc[q][0]); acc[q][1]=ffma2(u,wA.y,acc[q][1]); \
    acc[q][2]=ffma2(u,wB.x,acc[q][2]); acc[q][3]=ffma2(u,wB.y,acc[q][3]); \
    acc[q][4]=ffma2(u,wC.x,acc[q][4]); acc[q][5]=ffma2(u,wC.y,acc[q][5]); \
    acc[q][6]=ffma2(u,wD.x,acc[q][6]); acc[q][7]=ffma2(u,wD.y,acc[q][7]);

template<int C_OUT, int CHUNKS, int AST4>
__device__ __forceinline__ void gemm4x16(const float4* __restrict__ A, int e0,
                                         const float* __restrict__ W, int ccol,
                                         ull acc[4][8])
{
#pragma unroll 2
    for (int ch = 0; ch < CHUNKS; ch++) {
        float4 a0 = A[(e0     )*AST4 + ch];
        float4 a1 = A[(e0 + 4 )*AST4 + ch];
        float4 a2 = A[(e0 + 8 )*AST4 + ch];
        float4 a3 = A[(e0 + 12)*AST4 + ch];
#pragma unroll
        for (int kk = 0; kk < 4; kk++) {
            const ulonglong2* wp = (const ulonglong2*)(W + (ch*4+kk)*C_OUT + ccol);
            ulonglong2 wA = wp[0], wB = wp[1], wC = wp[2], wD = wp[3];
            float b; ull u;
            b = GETK(a0,kk); u = pk2(b,b); FMA_ROW(0,u)
            b = GETK(a1,kk); u = pk2(b,b); FMA_ROW(1,u)
            b = GETK(a2,kk); u = pk2(b,b); FMA_ROW(2,u)
            b = GETK(a3,kk); u = pk2(b,b); FMA_ROW(3,u)
        }
    }
}

// KD = weight K rows (9 / 67), MST = padded to mult of 4 (12 / 68)
template<bool FIRST, int KD, int C_OUT, int MST>
__global__ __launch_bounds__(2*C_OUT)
void conv_kernel(const float* __restrict__ x, const float* __restrict__ pos,
                 const float* __restrict__ normal,
                 const float* __restrict__ Wa, const float* __restrict__ ba,
                 const float* __restrict__ gam, const float* __restrict__ bet,
                 const float* __restrict__ Wb, const float* __restrict__ bb,
                 float* __restrict__ out)
{
    constexpr int T    = 2 * C_OUT;      // (C_OUT/16) col-groups * 32 lanes
    constexpr int NE   = 128;            // 8 nodes * 16 edges per block
    constexpr int MST4 = MST / 4;
    constexpr int HS   = C_OUT + 4;      // odd multiple of 16B -> conflict-free
    constexpr int HS4  = HS / 4;
    constexpr int XD   = KD - 3;         // x feature dim (non-first layers)

    extern __shared__ float sm[];
    float* Wa_s = sm;                          // MST * C_OUT
    float* Wb_s = Wa_s + MST*C_OUT;            // C_OUT * C_OUT
    float* ba_s = Wb_s + C_OUT*C_OUT;
    float* g_s  = ba_s + C_OUT;
    float* be_s = g_s  + C_OUT;
    float* bb_s = be_s + C_OUT;
    float* m_s  = bb_s + C_OUT;                // NE * MST
    float* h_s  = m_s  + NE*MST;               // NE * HS

    int tid  = threadIdx.x;
    int lane = tid & 31;
    int cg   = tid >> 5;

    // --- stage weights / biases ---
    {
        const float4* s1 = (const float4*)Wa; float4* d1 = (float4*)Wa_s;
        for (int i = tid; i < KD*C_OUT/4; i += T) d1[i] = s1[i];
        for (int i = KD*C_OUT/4 + tid; i < MST*C_OUT/4; i += T)
            d1[i] = make_float4(0.f,0.f,0.f,0.f);
        const float4* s2 = (const float4*)Wb; float4* d2 = (float4*)Wb_s;
        for (int i = tid; i < C_OUT*C_OUT/4; i += T) d2[i] = s2[i];
        for (int i = tid; i < C_OUT; i += T) {
            ba_s[i]=ba[i]; g_s[i]=gam[i]; be_s[i]=bet[i]; bb_s[i]=bb[i];
        }
    }

    // --- fill edge messages ---
    float4* m4 = (float4*)m_s;
    for (int i = tid; i < NE*MST4; i += T) {
        int edge = i / MST4;
        int c4   = i - edge*MST4;
        int node = blockIdx.x*8 + (edge >> 4);
        int j    = g_nbr[node*16 + (edge & 15)];
        float4 v;
        if (FIRST) {
            float pjx=pos[3*j], pjy=pos[3*j+1], pjz=pos[3*j+2];
            float njx=normal[3*j], njy=normal[3*j+1], njz=normal[3*j+2];
            float rx=pjx-pos[3*node], ry=pjy-pos[3*node+1], rz=pjz-pos[3*node+2];
            if      (c4 == 0) v = make_float4(pjx,pjy,pjz,njx);
            else if (c4 == 1) v = make_float4(njy,njz,rx,ry);
            else              v = make_float4(rz,0.f,0.f,0.f);
        } else {
            if (c4 < XD/4) v = ((const float4*)x)[j*(XD/4) + c4];
            else {
                float rx=pos[3*j]-pos[3*node], ry=pos[3*j+1]-pos[3*node+1],
                      rz=pos[3*j+2]-pos[3*node+2];
                v = make_float4(rx,ry,rz,0.f);
            }
        }
        m4[i] = v;
    }
    __syncthreads();

    int e0   = (lane>>2)*16 + (lane&3);   // local edge of q=0 (then +4,+8,+12)
    int ccol = cg*16;

    ull acc[4][8];

    // --- GEMM1 (+bias) ---
    {
        ull binit[8];
        const ulonglong2* bp = (const ulonglong2*)(ba_s + ccol);
#pragma unroll
        for (int w = 0; w < 4; w++) { ulonglong2 t2 = bp[w]; binit[2*w]=t2.x; binit[2*w+1]=t2.y; }
#pragma unroll
        for (int q=0;q<4;q++)
#pragma unroll
            for (int w=0;w<8;w++) acc[q][w]=binit[w];
    }
    gemm4x16<C_OUT, MST4, MST4>(m4, e0, Wa_s, ccol, acc);

    // --- GroupNorm(8-ch groups) + ReLU -> h ---
#pragma unroll
    for (int q = 0; q < 4; q++) {
        int edge = e0 + 4*q;
        float f[16];
#pragma unroll
        for (int w = 0; w < 8; w++) upk2(acc[q][w], f[2*w], f[2*w+1]);
#pragma unroll
        for (int g = 0; g < 2; g++) {
            float s = 0.f;
#pragma unroll
            for (int i2 = 0; i2 < 8; i2++) s += f[g*8+i2];
            float mu = s * 0.125f;
            float vs = 0.f;
#pragma unroll
            for (int i2 = 0; i2 < 8; i2++) { float d = f[g*8+i2]-mu; vs += d*d; }
            float inv = rsqrtf(vs*0.125f + 1e-5f);
#pragma unroll
            for (int i2 = 0; i2 < 8; i2++) {
                int c = ccol + g*8 + i2;
                f[g*8+i2] = fmaxf((f[g*8+i2]-mu)*inv*g_s[c] + be_s[c], 0.f);
            }
        }
        float4* hr = (float4*)h_s + edge*HS4 + cg*4;
        hr[0] = make_float4(f[0], f[1], f[2], f[3]);
        hr[1] = make_float4(f[4], f[5], f[6], f[7]);
        hr[2] = make_float4(f[8], f[9], f[10],f[11]);
        hr[3] = make_float4(f[12],f[13],f[14],f[15]);
    }
    __syncthreads();

    // --- GEMM2 (+bias) ---
    {
        ull binit[8];
        const ulonglong2* bp = (const ulonglong2*)(bb_s + ccol);
#pragma unroll
        for (int w = 0; w < 4; w++) { ulonglong2 t2 = bp[w]; binit[2*w]=t2.x; binit[2*w+1]=t2.y; }
#pragma unroll
        for (int q=0;q<4;q++)
#pragma unroll
            for (int w=0;w<8;w++) acc[q][w]=binit[w];
    }
    gemm4x16<C_OUT, C_OUT/4, HS4>((const float4*)h_s, e0, Wb_s, ccol, acc);

    // --- max over 16 neighbors + outer ReLU + store ---
    float v[16];
#pragma unroll
    for (int w=0;w<8;w++) upk2(acc[0][w], v[2*w], v[2*w+1]);
#pragma unroll
    for (int q=1;q<4;q++)
#pragma unroll
        for (int w=0;w<8;w++) {
            float a,b; upk2(acc[q][w],a,b);
            v[2*w]   = fmaxf(v[2*w],   a);
            v[2*w+1] = fmaxf(v[2*w+1], b);
        }
#pragma unroll
    for (int i2=0;i2<16;i2++) {
        v[i2] = fmaxf(v[i2], __shfl_xor_sync(0xffffffffu, v[i2], 1));
        v[i2] = fmaxf(v[i2], __shfl_xor_sync(0xffffffffu, v[i2], 2));
    }
    if ((lane&3) == 0) {
        int node = blockIdx.x*8 + (lane>>2);
        float4* o4 = (float4*)(out + (size_t)node*C_OUT + ccol);
        o4[0] = make_float4(fmaxf(v[0],0.f), fmaxf(v[1],0.f), fmaxf(v[2],0.f), fmaxf(v[3],0.f));
        o4[1] = make_float4(fmaxf(v[4],0.f), fmaxf(v[5],0.f), fmaxf(v[6],0.f), fmaxf(v[7],0.f));
        o4[2] = make_float4(fmaxf(v[8],0.f), fmaxf(v[9],0.f), fmaxf(v[10],0.f),fmaxf(v[11],0.f));
        o4[3] = make_float4(fmaxf(v[12],0.f),fmaxf(v[13],0.f),fmaxf(v[14],0.f),fmaxf(v[15],0.f));
    }
}

// ---------------------------------------------------------------------------

static constexpr int SM1 = (12*64  + 64*64   + 4*64  + 128*12 + 128*68 ) * 4; //  61,440 B
static constexpr int SM2 = (68*64  + 64*64   + 4*64  + 128*68 + 128*68 ) * 4; // 104,448 B
static constexpr int SM3 = (68*128 + 128*128 + 4*128 + 128*68 + 128*132) * 4; // 204,800 B

extern "C" void kernel_launch(void* const* d_in, const int* in_sizes, int n_in,
                              void* d_out, int out_size)
{
    const float* pos    = (const float*)d_in[0];
    const float* normal = (const float*)d_in[1];
    const float* W1a = (const float*)d_in[2];
    const float* b1a = (const float*)d_in[3];
    const float* g1  = (const float*)d_in[4];
    const float* be1 = (const float*)d_in[5];
    const float* W1b = (const float*)d_in[6];
    const float* b1b = (const float*)d_in[7];
    const float* W2a = (const float*)d_in[8];
    const float* b2a = (const float*)d_in[9];
    const float* g2  = (const float*)d_in[10];
    const float* be2 = (const float*)d_in[11];
    const float* W2b = (const float*)d_in[12];
    const float* b2b = (const float*)d_in[13];
    const float* W3a = (const float*)d_in[14];
    const float* b3a = (const float*)d_in[15];
    const float* g3  = (const float*)d_in[16];
    const float* be3 = (const float*)d_in[17];
    const float* W3b = (const float*)d_in[18];
    const float* b3b = (const float*)d_in[19];

    float* out = (float*)d_out;
    float* h1 = out;                            // [N,64]
    float* h2 = out + (size_t)NPTS * 64;        // [N,64]
    float* h3 = out + (size_t)NPTS * 128;       // [N,128]

    cudaFuncSetAttribute(conv_kernel<true,  9, 64, 12>,
                         cudaFuncAttributeMaxDynamicSharedMemorySize, SM1);
    cudaFuncSetAttribute(conv_kernel<false, 67, 64, 68>,
                         cudaFuncAttributeMaxDynamicSharedMemorySize, SM2);
    cudaFuncSetAttribute(conv_kernel<false, 67, 128, 68>,
                         cudaFuncAttributeMaxDynamicSharedMemorySize, SM3);

    knn_kernel<<<NPTS / 8, 256>>>(pos);

    conv_kernel<true, 9, 64, 12><<<NPTS*16/128, 128, SM1>>>(
        nullptr, pos, normal, W1a, b1a, g1, be1, W1b, b1b, h1);

    conv_kernel<false, 67, 64, 68><<<NPTS*16/128, 128, SM2>>>(
        h1, pos, nullptr, W2a, b2a, g2, be2, W2b, b2b, h2);

    conv_kernel<false, 67, 128, 68><<<NPTS*16/128, 256, SM3>>>(
        h2, pos, nullptr, W3a, b3a, g3, be3, W3b, b3b, h3);
}